// round 2
// baseline (speedup 1.0000x reference)
#include <cuda_runtime.h>

#define N 768
#define E_N 24576
#define CAP 128

// -------- device scratch (no allocations allowed) --------
static __device__ int   g_winner[N * N];     // last-wins edge id per (src,dst)
static __device__ int   g_cnt[N];            // winning-edge count per dst
static __device__ int   g_list[N * CAP];     // winning edge ids grouped by dst
static __device__ float g_evals[E_N * 64];   // edge MLP outputs [E,8,8]
static __device__ float g_mtr1[N * N * 8];   // walk contraction result
static __device__ int   g_idx64;             // 1 if edge_index is int64

// -------- dtype detection for edge_index --------
__global__ void k_detect(const int* __restrict__ ei32) {
    __shared__ int any;
    if (threadIdx.x == 0) any = 0;
    __syncthreads();
    // If the buffer is int64 little-endian, every odd 32-bit word (high half)
    // is 0 (values < 768). If it is int32, odd words are edge indices, almost
    // all nonzero. Scan 4096 words (safe under both interpretations).
    for (int j = threadIdx.x * 2 + 1; j < 4096; j += 512)
        if (ei32[j] != 0) any = 1;
    __syncthreads();
    if (threadIdx.x == 0) g_idx64 = (any == 0) ? 1 : 0;
}

__device__ __forceinline__ int load_idx(const void* ei, int pos, int use64) {
    if (use64) return (int)((const long long*)ei)[pos];
    return ((const int*)ei)[pos];
}

// -------- init --------
__global__ void k_init() {
    int idx = blockIdx.x * 1024 + threadIdx.x;   // 576*1024 == N*N exactly
    g_winner[idx] = -1;
    if (idx < N) g_cnt[idx] = 0;
}

// -------- last-write-wins dedup --------
__global__ void k_winner(const void* __restrict__ ei) {
    int e = blockIdx.x * 256 + threadIdx.x;
    if (e >= E_N) return;
    int use64 = g_idx64;
    int s = load_idx(ei, e, use64);
    int d = load_idx(ei, E_N + e, use64);
    atomicMax(&g_winner[s * N + d], e);
}

__global__ void k_build(const void* __restrict__ ei) {
    int e = blockIdx.x * 256 + threadIdx.x;
    if (e >= E_N) return;
    int use64 = g_idx64;
    int s = load_idx(ei, e, use64);
    int d = load_idx(ei, E_N + e, use64);
    if (g_winner[s * N + d] == e) {
        int slot = atomicAdd(&g_cnt[d], 1);
        if (slot < CAP) g_list[d * CAP + slot] = e;
    }
}

// -------- edge MLP: warp per edge, lane = neuron --------
__global__ void k_edge(const void* __restrict__ ei, const float* __restrict__ ea,
                       const float* __restrict__ feat,
                       const float* __restrict__ w0, const float* __restrict__ b0,
                       const float* __restrict__ w1, const float* __restrict__ b1,
                       const float* __restrict__ w2, const float* __restrict__ b2,
                       const float* __restrict__ w3, const float* __restrict__ b3) {
    // transposed weights in smem: t[i*OUT + o]  (conflict-free per-lane reads)
    __shared__ float t0[20 * 32], t1[32 * 32], t2[32 * 32], t3[32 * 64];
    __shared__ float sb0[32], sb1[32], sb2[32], sb3[64];
    __shared__ float xbuf[8][34];
    int tid = threadIdx.x;
    for (int j = tid; j < 640; j += 256) { int o = j / 20, i = j % 20; t0[i * 32 + o] = w0[j]; }
    for (int j = tid; j < 1024; j += 256) {
        int o = j >> 5, i = j & 31;
        t1[i * 32 + o] = w1[j];
        t2[i * 32 + o] = w2[j];
    }
    for (int j = tid; j < 2048; j += 256) { int o = j >> 5, i = j & 31; t3[i * 64 + o] = w3[j]; }
    if (tid < 32) { sb0[tid] = b0[tid]; sb1[tid] = b1[tid]; sb2[tid] = b2[tid]; }
    if (tid < 64) sb3[tid] = b3[tid];
    __syncthreads();

    int wid = tid >> 5, lane = tid & 31;
    int e = blockIdx.x * 8 + wid;      // grid = E_N/8 exactly
    int use64 = g_idx64;
    int s = load_idx(ei, e, use64);
    int d = load_idx(ei, E_N + e, use64);

    float* xb = xbuf[wid];
    if (lane < 4)       xb[lane] = ea[e * 4 + lane];
    else if (lane < 12) xb[lane] = feat[s * 8 + lane - 4];
    else if (lane < 20) xb[lane] = feat[d * 8 + lane - 12];
    __syncwarp();

    // layer 0: 20 -> 32
    float a = sb0[lane];
    #pragma unroll
    for (int i = 0; i < 20; i++) a += xb[i] * t0[i * 32 + lane];
    a = fmaxf(a, 0.f);
    __syncwarp(); xb[lane] = a; __syncwarp();

    // layer 1: 32 -> 32
    a = sb1[lane];
    #pragma unroll
    for (int i = 0; i < 32; i++) a += xb[i] * t1[i * 32 + lane];
    a = fmaxf(a, 0.f);
    __syncwarp(); xb[lane] = a; __syncwarp();

    // layer 2: 32 -> 32
    a = sb2[lane];
    #pragma unroll
    for (int i = 0; i < 32; i++) a += xb[i] * t2[i * 32 + lane];
    a = fmaxf(a, 0.f);
    __syncwarp(); xb[lane] = a; __syncwarp();

    // layer 3: 32 -> 64 (no relu), two outputs per lane
    float a0 = sb3[lane], a1 = sb3[lane + 32];
    #pragma unroll
    for (int i = 0; i < 32; i++) {
        float xv = xb[i];
        a0 += xv * t3[i * 64 + lane];
        a1 += xv * t3[i * 64 + lane + 32];
    }
    g_evals[e * 64 + lane]      = a0;
    g_evals[e * 64 + 32 + lane] = a1;
}

// -------- walk contraction: CTA per dst-column k, thread handles 3 rows --------
__global__ void k_walk(const float* __restrict__ mtr, const void* __restrict__ ei) {
    int k = blockIdx.x;
    int tid = threadIdx.x;
    __shared__ float sM[8 * 64];
    __shared__ int ssrc[8];
    int cnt = g_cnt[k];
    int use64 = g_idx64;

    float acc[3][8];
    #pragma unroll
    for (int r = 0; r < 3; r++)
        #pragma unroll
        for (int t = 0; t < 8; t++) acc[r][t] = 0.f;

    for (int base = 0; base < cnt; base += 8) {
        int nc = min(8, cnt - base);
        __syncthreads();
        for (int t = tid; t < nc * 64; t += 256) {
            int e = g_list[k * CAP + base + (t >> 6)];
            sM[t] = g_evals[e * 64 + (t & 63)];
        }
        if (tid < nc) ssrc[tid] = load_idx(ei, g_list[k * CAP + base + tid], use64);
        __syncthreads();

        for (int c = 0; c < nc; c++) {
            int s = ssrc[c];
            float av[3][8];
            #pragma unroll
            for (int r = 0; r < 3; r++) {
                int i = tid + (r << 8);
                const float4* p = (const float4*)&mtr[(i * N + s) * 8];
                float4 v0 = p[0], v1 = p[1];
                av[r][0] = v0.x; av[r][1] = v0.y; av[r][2] = v0.z; av[r][3] = v0.w;
                av[r][4] = v1.x; av[r][5] = v1.y; av[r][6] = v1.z; av[r][7] = v1.w;
            }
            #pragma unroll
            for (int cc = 0; cc < 8; cc++) {
                const float4* mp = (const float4*)&sM[c * 64 + cc * 8];
                float4 m0 = mp[0], m1 = mp[1];
                #pragma unroll
                for (int r = 0; r < 3; r++) {
                    float x = av[r][cc];
                    acc[r][0] += x * m0.x; acc[r][1] += x * m0.y;
                    acc[r][2] += x * m0.z; acc[r][3] += x * m0.w;
                    acc[r][4] += x * m1.x; acc[r][5] += x * m1.y;
                    acc[r][6] += x * m1.z; acc[r][7] += x * m1.w;
                }
            }
        }
    }
    #pragma unroll
    for (int r = 0; r < 3; r++) {
        int i = tid + (r << 8);
        float4 o0, o1;
        o0.x = acc[r][0] * 0.125f; o0.y = acc[r][1] * 0.125f;
        o0.z = acc[r][2] * 0.125f; o0.w = acc[r][3] * 0.125f;
        o1.x = acc[r][4] * 0.125f; o1.y = acc[r][5] * 0.125f;
        o1.z = acc[r][6] * 0.125f; o1.w = acc[r][7] * 0.125f;
        *(float4*)&g_mtr1[(i * N + k) * 8]     = o0;
        *(float4*)&g_mtr1[(i * N + k) * 8 + 4] = o1;
    }
}

// -------- output MLP: thread per (i,k) row, weights broadcast from smem --------
__global__ void k_out(const float* __restrict__ mtr, const float* __restrict__ feat,
                      float* __restrict__ out,
                      const float* __restrict__ w0, const float* __restrict__ b0,
                      const float* __restrict__ w1, const float* __restrict__ b1,
                      const float* __restrict__ w2, const float* __restrict__ b2,
                      const float* __restrict__ w3, const float* __restrict__ b3) {
    __shared__ float sw0[32 * 33], sw1[32 * 32], sw2[32 * 32], sw3[8 * 32];
    __shared__ float sb0[32], sb1[32], sb2[32], sb3[8];
    int tid = threadIdx.x;
    for (int j = tid; j < 1056; j += 256) sw0[j] = w0[j];
    for (int j = tid; j < 1024; j += 256) { sw1[j] = w1[j]; sw2[j] = w2[j]; }
    sw3[tid] = w3[tid];   // exactly 256
    if (tid < 32) { sb0[tid] = b0[tid]; sb1[tid] = b1[tid]; sb2[tid] = b2[tid]; }
    if (tid < 8) sb3[tid] = b3[tid];
    __syncthreads();

    int i = blockIdx.y;
    int k = blockIdx.x * 256 + tid;
    int base  = (i * N + k) * 8;
    int baseT = (k * N + i) * 8;

    float x[33];
    {
        float4 v;
        v = *(const float4*)&g_mtr1[base];      x[0]=v.x;  x[1]=v.y;  x[2]=v.z;  x[3]=v.w;
        v = *(const float4*)&g_mtr1[base + 4];  x[4]=v.x;  x[5]=v.y;  x[6]=v.z;  x[7]=v.w;
        v = *(const float4*)&g_mtr1[baseT];     x[8]=v.x;  x[9]=v.y;  x[10]=v.z; x[11]=v.w;
        v = *(const float4*)&g_mtr1[baseT + 4]; x[12]=v.x; x[13]=v.y; x[14]=v.z; x[15]=v.w;
        v = *(const float4*)&feat[k * 8];       x[16]=v.x; x[17]=v.y; x[18]=v.z; x[19]=v.w;
        v = *(const float4*)&feat[k * 8 + 4];   x[20]=v.x; x[21]=v.y; x[22]=v.z; x[23]=v.w;
        v = *(const float4*)&feat[i * 8];       x[24]=v.x; x[25]=v.y; x[26]=v.z; x[27]=v.w;
        v = *(const float4*)&feat[i * 8 + 4];   x[28]=v.x; x[29]=v.y; x[30]=v.z; x[31]=v.w;
        x[32] = (i == k) ? 1.0f : 0.0f;
    }

    float h[32];
    #pragma unroll
    for (int o = 0; o < 32; o++) {
        float a = sb0[o];
        #pragma unroll
        for (int j = 0; j < 33; j++) a += x[j] * sw0[o * 33 + j];
        h[o] = fmaxf(a, 0.0f);
    }
    float h2[32];
    #pragma unroll
    for (int o = 0; o < 32; o++) {
        float a = sb1[o];
        const float4* wr = (const float4*)&sw1[o * 32];
        #pragma unroll
        for (int j = 0; j < 8; j++) {
            float4 w = wr[j];
            a += h[4*j]*w.x + h[4*j+1]*w.y + h[4*j+2]*w.z + h[4*j+3]*w.w;
        }
        h2[o] = fmaxf(a, 0.0f);
    }
    #pragma unroll
    for (int o = 0; o < 32; o++) {
        float a = sb2[o];
        const float4* wr = (const float4*)&sw2[o * 32];
        #pragma unroll
        for (int j = 0; j < 8; j++) {
            float4 w = wr[j];
            a += h2[4*j]*w.x + h2[4*j+1]*w.y + h2[4*j+2]*w.z + h2[4*j+3]*w.w;
        }
        h[o] = fmaxf(a, 0.0f);
    }
    float y[8];
    #pragma unroll
    for (int o = 0; o < 8; o++) {
        float a = sb3[o];
        const float4* wr = (const float4*)&sw3[o * 32];
        #pragma unroll
        for (int j = 0; j < 8; j++) {
            float4 w = wr[j];
            a += h[4*j]*w.x + h[4*j+1]*w.y + h[4*j+2]*w.z + h[4*j+3]*w.w;
        }
        y[o] = a;
    }
    const float4* mp = (const float4*)&mtr[base];
    float4 m0 = mp[0], m1 = mp[1];
    float4 o0, o1;
    o0.x = m0.x + y[0]; o0.y = m0.y + y[1]; o0.z = m0.z + y[2]; o0.w = m0.w + y[3];
    o1.x = m1.x + y[4]; o1.y = m1.y + y[5]; o1.z = m1.z + y[6]; o1.w = m1.w + y[7];
    *(float4*)&out[base]     = o0;
    *(float4*)&out[base + 4] = o1;
}

extern "C" void kernel_launch(void* const* d_in, const int* in_sizes, int n_in,
                              void* d_out, int out_size) {
    const float* mtr  = (const float*)d_in[0];
    const float* feat = (const float*)d_in[1];
    const void*  ei   = d_in[2];
    const float* ea   = (const float*)d_in[3];
    const float* ew0 = (const float*)d_in[4],  *eb0 = (const float*)d_in[5];
    const float* ew1 = (const float*)d_in[6],  *eb1 = (const float*)d_in[7];
    const float* ew2 = (const float*)d_in[8],  *eb2 = (const float*)d_in[9];
    const float* ew3 = (const float*)d_in[10], *eb3 = (const float*)d_in[11];
    const float* ow0 = (const float*)d_in[12], *ob0 = (const float*)d_in[13];
    const float* ow1 = (const float*)d_in[14], *ob1 = (const float*)d_in[15];
    const float* ow2 = (const float*)d_in[16], *ob2 = (const float*)d_in[17];
    const float* ow3 = (const float*)d_in[18], *ob3 = (const float*)d_in[19];
    float* out = (float*)d_out;

    k_detect<<<1, 256>>>((const int*)ei);
    k_init<<<(N * N) / 1024, 1024>>>();
    k_winner<<<E_N / 256, 256>>>(ei);
    k_build<<<E_N / 256, 256>>>(ei);
    k_edge<<<E_N / 8, 256>>>(ei, ea, feat, ew0, eb0, ew1, eb1, ew2, eb2, ew3, eb3);
    k_walk<<<N, 256>>>(mtr, ei);
    dim3 g(3, N);
    k_out<<<g, 256>>>(mtr, feat, out, ow0, ob0, ow1, ob1, ow2, ob2, ow3, ob3);
}

// round 7
// speedup vs baseline: 2.0598x; 2.0598x over previous
#include <cuda_runtime.h>

#define N 768
#define E_N 24576
#define CAP 128

// -------- device scratch --------
static __device__ int   g_winner[N * N];
static __device__ int   g_cnt[N];
static __device__ int   g_list[N * CAP];
static __device__ float g_evals[E_N * 64];           // edge MLP out [E,8,8]
static __device__ float g_mtr1[N * N * 8];           // walk result
static __device__ float g_mtrT[N * N * 8];           // mtr transposed: [j][i][c]
static __device__ int   g_idx64;

typedef unsigned long long u64;

// -------- f32x2 helpers --------
__device__ __forceinline__ u64 pk2(float lo, float hi) {
    u64 r;
    asm("mov.b64 %0, {%1, %2};" : "=l"(r) : "r"(__float_as_uint(lo)), "r"(__float_as_uint(hi)));
    return r;
}
__device__ __forceinline__ void upk2(u64 p, float& lo, float& hi) {
    unsigned a, b;
    asm("mov.b64 {%0, %1}, %2;" : "=r"(a), "=r"(b) : "l"(p));
    lo = __uint_as_float(a); hi = __uint_as_float(b);
}
__device__ __forceinline__ u64 fma2(u64 a, u64 b, u64 c) {
    u64 d;
    asm("fma.rn.f32x2 %0, %1, %2, %3;" : "=l"(d) : "l"(a), "l"(b), "l"(c));
    return d;
}
__device__ __forceinline__ u64 mul2(u64 a, u64 b) {
    u64 d;
    asm("mul.rn.f32x2 %0, %1, %2;" : "=l"(d) : "l"(a), "l"(b));
    return d;
}
__device__ __forceinline__ u64 relu2(u64 p) {
    float lo, hi; upk2(p, lo, hi);
    return pk2(fmaxf(lo, 0.f), fmaxf(hi, 0.f));
}

__device__ __forceinline__ int load_idx(const void* ei, int pos, int use64) {
    if (use64) return (int)((const long long*)ei)[pos];
    return ((const int*)ei)[pos];
}

// -------- init (+ int64 detection in extra block) --------
__global__ void k_init(const int* __restrict__ ei32) {
    if (blockIdx.x == 576) {
        __shared__ int any;
        if (threadIdx.x == 0) any = 0;
        __syncthreads();
        for (int j = threadIdx.x * 2 + 1; j < 4096; j += 2048)
            if (ei32[j] != 0) any = 1;
        __syncthreads();
        if (threadIdx.x == 0) g_idx64 = (any == 0) ? 1 : 0;
        return;
    }
    int idx = blockIdx.x * 1024 + threadIdx.x;
    g_winner[idx] = -1;
    if (idx < N) g_cnt[idx] = 0;
}

__global__ void k_winner(const void* __restrict__ ei) {
    int e = blockIdx.x * 256 + threadIdx.x;
    int use64 = g_idx64;
    int s = load_idx(ei, e, use64);
    int d = load_idx(ei, E_N + e, use64);
    atomicMax(&g_winner[s * N + d], e);
}

__global__ void k_build(const void* __restrict__ ei) {
    int e = blockIdx.x * 256 + threadIdx.x;
    int use64 = g_idx64;
    int s = load_idx(ei, e, use64);
    int d = load_idx(ei, E_N + e, use64);
    if (g_winner[s * N + d] == e) {
        int slot = atomicAdd(&g_cnt[d], 1);
        if (slot < CAP) g_list[d * CAP + slot] = e;
    }
}

// -------- edge MLP (blocks < 3072) + mtr transpose (blocks >= 3072) --------
__global__ void k_edge(const void* __restrict__ ei, const float* __restrict__ ea,
                       const float* __restrict__ feat, const float* __restrict__ mtr,
                       const float* __restrict__ w0, const float* __restrict__ b0,
                       const float* __restrict__ w1, const float* __restrict__ b1,
                       const float* __restrict__ w2, const float* __restrict__ b2,
                       const float* __restrict__ w3, const float* __restrict__ b3) {
    if (blockIdx.x >= 3072) {
        // transpose role: one row i of mtr -> column i of g_mtrT
        int i = blockIdx.x - 3072;
        #pragma unroll
        for (int jj = 0; jj < 3; jj++) {
            int j = threadIdx.x + jj * 256;
            const float4* p = (const float4*)&mtr[(i * N + j) * 8];
            float4 v0 = p[0], v1 = p[1];
            float4* q = (float4*)&g_mtrT[(j * N + i) * 8];
            q[0] = v0; q[1] = v1;
        }
        return;
    }
    __shared__ float t0[20 * 32], t1[32 * 32], t2[32 * 32], t3[32 * 64];
    __shared__ float sb0[32], sb1[32], sb2[32], sb3[64];
    __shared__ float xbuf[8][34];
    int tid = threadIdx.x;
    for (int j = tid; j < 640; j += 256) { int o = j / 20, i = j % 20; t0[i * 32 + o] = w0[j]; }
    for (int j = tid; j < 1024; j += 256) {
        int o = j >> 5, i = j & 31;
        t1[i * 32 + o] = w1[j];
        t2[i * 32 + o] = w2[j];
    }
    for (int j = tid; j < 2048; j += 256) { int o = j >> 5, i = j & 31; t3[i * 64 + o] = w3[j]; }
    if (tid < 32) { sb0[tid] = b0[tid]; sb1[tid] = b1[tid]; sb2[tid] = b2[tid]; }
    if (tid < 64) sb3[tid] = b3[tid];
    __syncthreads();

    int wid = tid >> 5, lane = tid & 31;
    int e = blockIdx.x * 8 + wid;
    int use64 = g_idx64;
    int s = load_idx(ei, e, use64);
    int d = load_idx(ei, E_N + e, use64);

    float* xb = xbuf[wid];
    if (lane < 4)       xb[lane] = ea[e * 4 + lane];
    else if (lane < 12) xb[lane] = feat[s * 8 + lane - 4];
    else if (lane < 20) xb[lane] = feat[d * 8 + lane - 12];
    __syncwarp();

    float a = sb0[lane];
    #pragma unroll
    for (int i = 0; i < 20; i++) a += xb[i] * t0[i * 32 + lane];
    a = fmaxf(a, 0.f);
    __syncwarp(); xb[lane] = a; __syncwarp();

    a = sb1[lane];
    #pragma unroll
    for (int i = 0; i < 32; i++) a += xb[i] * t1[i * 32 + lane];
    a = fmaxf(a, 0.f);
    __syncwarp(); xb[lane] = a; __syncwarp();

    a = sb2[lane];
    #pragma unroll
    for (int i = 0; i < 32; i++) a += xb[i] * t2[i * 32 + lane];
    a = fmaxf(a, 0.f);
    __syncwarp(); xb[lane] = a; __syncwarp();

    float a0 = sb3[lane], a1 = sb3[lane + 32];
    #pragma unroll
    for (int i = 0; i < 32; i++) {
        float xv = xb[i];
        a0 += xv * t3[i * 64 + lane];
        a1 += xv * t3[i * 64 + lane + 32];
    }
    g_evals[e * 64 + lane]      = a0;
    g_evals[e * 64 + 32 + lane] = a1;
}

// -------- walk contraction: coalesced via g_mtrT, f32x2 packed over t --------
__global__ void k_walk(const void* __restrict__ ei) {
    int k = blockIdx.x;
    int tid = threadIdx.x;
    __shared__ __align__(16) float sM[8 * 64];
    __shared__ int ssrc[8];
    int cnt = g_cnt[k];
    int use64 = g_idx64;

    u64 acc[3][4];
    #pragma unroll
    for (int r = 0; r < 3; r++)
        #pragma unroll
        for (int t = 0; t < 4; t++) acc[r][t] = 0ULL;

    for (int base = 0; base < cnt; base += 8) {
        int nc = min(8, cnt - base);
        __syncthreads();
        for (int t = tid; t < nc * 64; t += 256) {
            int e = g_list[k * CAP + base + (t >> 6)];
            sM[t] = g_evals[e * 64 + (t & 63)];
        }
        if (tid < nc) ssrc[tid] = load_idx(ei, g_list[k * CAP + base + tid], use64);
        __syncthreads();

        for (int c = 0; c < nc; c++) {
            int s = ssrc[c];
            float av[3][8];
            #pragma unroll
            for (int r = 0; r < 3; r++) {
                int i = tid + (r << 8);
                const float4* p = (const float4*)&g_mtrT[(s * N + i) * 8];  // coalesced
                float4 v0 = p[0], v1 = p[1];
                av[r][0] = v0.x; av[r][1] = v0.y; av[r][2] = v0.z; av[r][3] = v0.w;
                av[r][4] = v1.x; av[r][5] = v1.y; av[r][6] = v1.z; av[r][7] = v1.w;
            }
            #pragma unroll
            for (int cc = 0; cc < 8; cc++) {
                const ulonglong2* mp = (const ulonglong2*)&sM[c * 64 + cc * 8];
                ulonglong2 ma = mp[0], mb = mp[1];
                #pragma unroll
                for (int r = 0; r < 3; r++) {
                    u64 dv = pk2(av[r][cc], av[r][cc]);
                    acc[r][0] = fma2(dv, ma.x, acc[r][0]);
                    acc[r][1] = fma2(dv, ma.y, acc[r][1]);
                    acc[r][2] = fma2(dv, mb.x, acc[r][2]);
                    acc[r][3] = fma2(dv, mb.y, acc[r][3]);
                }
            }
        }
    }
    u64 eighth = pk2(0.125f, 0.125f);
    #pragma unroll
    for (int r = 0; r < 3; r++) {
        int i = tid + (r << 8);
        float4 o0, o1;
        upk2(mul2(acc[r][0], eighth), o0.x, o0.y);
        upk2(mul2(acc[r][1], eighth), o0.z, o0.w);
        upk2(mul2(acc[r][2], eighth), o1.x, o1.y);
        upk2(mul2(acc[r][3], eighth), o1.z, o1.w);
        *(float4*)&g_mtr1[(i * N + k) * 8]     = o0;
        *(float4*)&g_mtr1[(i * N + k) * 8 + 4] = o1;
    }
}

// -------- output MLP: 2 rows/thread, f32x2, dup-weight LDS.128 --------
__global__ void __launch_bounds__(128) k_out(
        const float* __restrict__ mtr, const float* __restrict__ feat,
        float* __restrict__ out,
        const float* __restrict__ w0, const float* __restrict__ b0,
        const float* __restrict__ w1, const float* __restrict__ b1,
        const float* __restrict__ w2, const float* __restrict__ b2,
        const float* __restrict__ w3, const float* __restrict__ b3) {
    // duplicated weight packs, transposed: wd[j*OUT + o] = (w[o][j], w[o][j])
    __shared__ __align__(16) u64 wd0[33 * 32], wd1[32 * 32], wd2[32 * 32], wd3[32 * 8];
    __shared__ __align__(16) u64 bd0[32], bd1[32], bd2[32], bd3[8];
    int tid = threadIdx.x;
    for (int t = tid; t < 1056; t += 128) { int j = t >> 5, o = t & 31; float w = w0[o * 33 + j]; wd0[t] = pk2(w, w); }
    for (int t = tid; t < 1024; t += 128) {
        int j = t >> 5, o = t & 31;
        float wa = w1[o * 32 + j]; wd1[t] = pk2(wa, wa);
        float wb = w2[o * 32 + j]; wd2[t] = pk2(wb, wb);
    }
    for (int t = tid; t < 256; t += 128) { int j = t >> 3, o = t & 7; float w = w3[o * 32 + j]; wd3[t] = pk2(w, w); }
    if (tid < 32) {
        float v;
        v = b0[tid]; bd0[tid] = pk2(v, v);
        v = b1[tid]; bd1[tid] = pk2(v, v);
        v = b2[tid]; bd2[tid] = pk2(v, v);
        if (tid < 8) { v = b3[tid]; bd3[tid] = pk2(v, v); }
    }
    __syncthreads();

    int i  = blockIdx.y;
    int k1 = blockIdx.x * 256 + tid;
    int k2 = k1 + 128;
    int base1 = (i * N + k1) * 8, base2 = (i * N + k2) * 8;
    int bT1 = (k1 * N + i) * 8, bT2 = (k2 * N + i) * 8;

    u64 xp[33];
    {
        float4 a0 = *(const float4*)&g_mtr1[base1], a1 = *(const float4*)&g_mtr1[base1 + 4];
        float4 c0 = *(const float4*)&g_mtr1[base2], c1 = *(const float4*)&g_mtr1[base2 + 4];
        xp[0] = pk2(a0.x, c0.x); xp[1] = pk2(a0.y, c0.y); xp[2] = pk2(a0.z, c0.z); xp[3] = pk2(a0.w, c0.w);
        xp[4] = pk2(a1.x, c1.x); xp[5] = pk2(a1.y, c1.y); xp[6] = pk2(a1.z, c1.z); xp[7] = pk2(a1.w, c1.w);
        a0 = *(const float4*)&g_mtr1[bT1]; a1 = *(const float4*)&g_mtr1[bT1 + 4];
        c0 = *(const float4*)&g_mtr1[bT2]; c1 = *(const float4*)&g_mtr1[bT2 + 4];
        xp[8]  = pk2(a0.x, c0.x); xp[9]  = pk2(a0.y, c0.y); xp[10] = pk2(a0.z, c0.z); xp[11] = pk2(a0.w, c0.w);
        xp[12] = pk2(a1.x, c1.x); xp[13] = pk2(a1.y, c1.y); xp[14] = pk2(a1.z, c1.z); xp[15] = pk2(a1.w, c1.w);
        a0 = *(const float4*)&feat[k1 * 8]; a1 = *(const float4*)&feat[k1 * 8 + 4];
        c0 = *(const float4*)&feat[k2 * 8]; c1 = *(const float4*)&feat[k2 * 8 + 4];
        xp[16] = pk2(a0.x, c0.x); xp[17] = pk2(a0.y, c0.y); xp[18] = pk2(a0.z, c0.z); xp[19] = pk2(a0.w, c0.w);
        xp[20] = pk2(a1.x, c1.x); xp[21] = pk2(a1.y, c1.y); xp[22] = pk2(a1.z, c1.z); xp[23] = pk2(a1.w, c1.w);
        a0 = *(const float4*)&feat[i * 8]; a1 = *(const float4*)&feat[i * 8 + 4];
        xp[24] = pk2(a0.x, a0.x); xp[25] = pk2(a0.y, a0.y); xp[26] = pk2(a0.z, a0.z); xp[27] = pk2(a0.w, a0.w);
        xp[28] = pk2(a1.x, a1.x); xp[29] = pk2(a1.y, a1.y); xp[30] = pk2(a1.z, a1.z); xp[31] = pk2(a1.w, a1.w);
        xp[32] = pk2(i == k1 ? 1.f : 0.f, i == k2 ? 1.f : 0.f);
    }

    u64 acc[32], h[32];
    // layer 0: 33 -> 32
    {
        const ulonglong2* B = (const ulonglong2*)bd0;
        #pragma unroll
        for (int oo = 0; oo < 16; oo++) { ulonglong2 b = B[oo]; acc[2*oo] = b.x; acc[2*oo+1] = b.y; }
        const ulonglong2* W = (const ulonglong2*)wd0;
        #pragma unroll
        for (int j = 0; j < 33; j++) {
            u64 xj = xp[j];
            #pragma unroll
            for (int oo = 0; oo < 16; oo++) {
                ulonglong2 w = W[j * 16 + oo];
                acc[2*oo]   = fma2(xj, w.x, acc[2*oo]);
                acc[2*oo+1] = fma2(xj, w.y, acc[2*oo+1]);
            }
        }
        #pragma unroll
        for (int o = 0; o < 32; o++) h[o] = relu2(acc[o]);
    }
    // layer 1: 32 -> 32
    {
        const ulonglong2* B = (const ulonglong2*)bd1;
        #pragma unroll
        for (int oo = 0; oo < 16; oo++) { ulonglong2 b = B[oo]; acc[2*oo] = b.x; acc[2*oo+1] = b.y; }
        const ulonglong2* W = (const ulonglong2*)wd1;
        #pragma unroll
        for (int j = 0; j < 32; j++) {
            u64 xj = h[j];
            #pragma unroll
            for (int oo = 0; oo < 16; oo++) {
                ulonglong2 w = W[j * 16 + oo];
                acc[2*oo]   = fma2(xj, w.x, acc[2*oo]);
                acc[2*oo+1] = fma2(xj, w.y, acc[2*oo+1]);
            }
        }
        #pragma unroll
        for (int o = 0; o < 32; o++) acc[o] = relu2(acc[o]);
    }
    // layer 2: 32 -> 32
    {
        const ulonglong2* B = (const ulonglong2*)bd2;
        #pragma unroll
        for (int oo = 0; oo < 16; oo++) { ulonglong2 b = B[oo]; h[2*oo] = b.x; h[2*oo+1] = b.y; }
        const ulonglong2* W = (const ulonglong2*)wd2;
        #pragma unroll
        for (int j = 0; j < 32; j++) {
            u64 xj = acc[j];
            #pragma unroll
            for (int oo = 0; oo < 16; oo++) {
                ulonglong2 w = W[j * 16 + oo];
                h[2*oo]   = fma2(xj, w.x, h[2*oo]);
                h[2*oo+1] = fma2(xj, w.y, h[2*oo+1]);
            }
        }
        #pragma unroll
        for (int o = 0; o < 32; o++) h[o] = relu2(h[o]);
    }
    // layer 3: 32 -> 8
    u64 y[8];
    {
        const ulonglong2* B = (const ulonglong2*)bd3;
        #pragma unroll
        for (int oo = 0; oo < 4; oo++) { ulonglong2 b = B[oo]; y[2*oo] = b.x; y[2*oo+1] = b.y; }
        const ulonglong2* W = (const ulonglong2*)wd3;
        #pragma unroll
        for (int j = 0; j < 32; j++) {
            u64 xj = h[j];
            #pragma unroll
            for (int oo = 0; oo < 4; oo++) {
                ulonglong2 w = W[j * 4 + oo];
                y[2*oo]   = fma2(xj, w.x, y[2*oo]);
                y[2*oo+1] = fma2(xj, w.y, y[2*oo+1]);
            }
        }
    }
    // residual add + store both rows
    {
        float yr1[8], yr2[8];
        #pragma unroll
        for (int c = 0; c < 8; c++) upk2(y[c], yr1[c], yr2[c]);
        float4 m0 = *(const float4*)&mtr[base1], m1 = *(const float4*)&mtr[base1 + 4];
        float4 o0, o1;
        o0.x = m0.x + yr1[0]; o0.y = m0.y + yr1[1]; o0.z = m0.z + yr1[2]; o0.w = m0.w + yr1[3];
        o1.x = m1.x + yr1[4]; o1.y = m1.y + yr1[5]; o1.z = m1.z + yr1[6]; o1.w = m1.w + yr1[7];
        *(float4*)&out[base1] = o0; *(float4*)&out[base1 + 4] = o1;
        m0 = *(const float4*)&mtr[base2]; m1 = *(const float4*)&mtr[base2 + 4];
        o0.x = m0.x + yr2[0]; o0.y = m0.y + yr2[1]; o0.z = m0.z + yr2[2]; o0.w = m0.w + yr2[3];
        o1.x = m1.x + yr2[4]; o1.y = m1.y + yr2[5]; o1.z = m1.z + yr2[6]; o1.w = m1.w + yr2[7];
        *(float4*)&out[base2] = o0; *(float4*)&out[base2 + 4] = o1;
    }
}

extern "C" void kernel_launch(void* const* d_in, const int* in_sizes, int n_in,
                              void* d_out, int out_size) {
    const float* mtr  = (const float*)d_in[0];
    const float* feat = (const float*)d_in[1];
    const void*  ei   = d_in[2];
    const float* ea   = (const float*)d_in[3];
    const float* ew0 = (const float*)d_in[4],  *eb0 = (const float*)d_in[5];
    const float* ew1 = (const float*)d_in[6],  *eb1 = (const float*)d_in[7];
    const float* ew2 = (const float*)d_in[8],  *eb2 = (const float*)d_in[9];
    const float* ew3 = (const float*)d_in[10], *eb3 = (const float*)d_in[11];
    const float* ow0 = (const float*)d_in[12], *ob0 = (const float*)d_in[13];
    const float* ow1 = (const float*)d_in[14], *ob1 = (const float*)d_in[15];
    const float* ow2 = (const float*)d_in[16], *ob2 = (const float*)d_in[17];
    const float* ow3 = (const float*)d_in[18], *ob3 = (const float*)d_in[19];
    float* out = (float*)d_out;

    k_init<<<577, 1024>>>((const int*)ei);
    k_winner<<<E_N / 256, 256>>>(ei);
    k_build<<<E_N / 256, 256>>>(ei);
    k_edge<<<3072 + 768, 256>>>(ei, ea, feat, mtr, ew0, eb0, ew1, eb1, ew2, eb2, ew3, eb3);
    k_walk<<<N, 256>>>(ei);
    dim3 g(3, N);
    k_out<<<g, 128>>>(mtr, feat, out, ow0, ob0, ow1, ob1, ow2, ob2, ow3, ob3);
}

// round 9
// speedup vs baseline: 2.3275x; 1.1299x over previous
#include <cuda_runtime.h>

#define N 768
#define E_N 24576
#define CAP 128

// -------- device scratch --------
static __device__ int   g_winner[N * N];
static __device__ int   g_cnt[N];
static __device__ int   g_list[N * CAP];
static __device__ float g_evals[E_N * 64];           // edge MLP out [E,8,8]
static __device__ float g_mtr1[N * N * 8];           // walk result
static __device__ float g_mtrT[N * N * 8];           // mtr transposed: [j][i][c]
static __device__ int   g_idx64;

typedef unsigned long long u64;

// -------- f32x2 helpers --------
__device__ __forceinline__ u64 pk2(float lo, float hi) {
    u64 r;
    asm("mov.b64 %0, {%1, %2};" : "=l"(r) : "r"(__float_as_uint(lo)), "r"(__float_as_uint(hi)));
    return r;
}
__device__ __forceinline__ void upk2(u64 p, float& lo, float& hi) {
    unsigned a, b;
    asm("mov.b64 {%0, %1}, %2;" : "=r"(a), "=r"(b) : "l"(p));
    lo = __uint_as_float(a); hi = __uint_as_float(b);
}
__device__ __forceinline__ u64 fma2(u64 a, u64 b, u64 c) {
    u64 d;
    asm("fma.rn.f32x2 %0, %1, %2, %3;" : "=l"(d) : "l"(a), "l"(b), "l"(c));
    return d;
}
__device__ __forceinline__ u64 mul2(u64 a, u64 b) {
    u64 d;
    asm("mul.rn.f32x2 %0, %1, %2;" : "=l"(d) : "l"(a), "l"(b));
    return d;
}
__device__ __forceinline__ u64 relu2(u64 p) {
    float lo, hi; upk2(p, lo, hi);
    return pk2(fmaxf(lo, 0.f), fmaxf(hi, 0.f));
}

__device__ __forceinline__ int load_idx(const void* ei, int pos, int use64) {
    if (use64) return (int)((const long long*)ei)[pos];
    return ((const int*)ei)[pos];
}

// -------- init (+ int64 detection in extra block) --------
__global__ void k_init(const int* __restrict__ ei32) {
    if (blockIdx.x == 576) {
        __shared__ int any;
        if (threadIdx.x == 0) any = 0;
        __syncthreads();
        for (int j = threadIdx.x * 2 + 1; j < 4096; j += 2048)
            if (ei32[j] != 0) any = 1;
        __syncthreads();
        if (threadIdx.x == 0) g_idx64 = (any == 0) ? 1 : 0;
        return;
    }
    int idx = blockIdx.x * 1024 + threadIdx.x;
    g_winner[idx] = -1;
    if (idx < N) g_cnt[idx] = 0;
}

__global__ void k_winner(const void* __restrict__ ei) {
    int e = blockIdx.x * 256 + threadIdx.x;
    int use64 = g_idx64;
    int s = load_idx(ei, e, use64);
    int d = load_idx(ei, E_N + e, use64);
    atomicMax(&g_winner[s * N + d], e);
}

__global__ void k_build(const void* __restrict__ ei) {
    int e = blockIdx.x * 256 + threadIdx.x;
    int use64 = g_idx64;
    int s = load_idx(ei, e, use64);
    int d = load_idx(ei, E_N + e, use64);
    if (g_winner[s * N + d] == e) {
        int slot = atomicAdd(&g_cnt[d], 1);
        if (slot < CAP) g_list[d * CAP + slot] = e;
    }
}

// -------- edge MLP: thread per edge, broadcast-LDS weights (blocks < 96);
//          mtr transpose (blocks >= 96) --------
__global__ void k_edge(const void* __restrict__ ei, const float* __restrict__ ea,
                       const float* __restrict__ feat, const float* __restrict__ mtr,
                       const float* __restrict__ w0, const float* __restrict__ b0,
                       const float* __restrict__ w1, const float* __restrict__ b1,
                       const float* __restrict__ w2, const float* __restrict__ b2,
                       const float* __restrict__ w3, const float* __restrict__ b3) {
    if (blockIdx.x >= 96) {
        // transpose role: one row i of mtr -> column i of g_mtrT
        int i = blockIdx.x - 96;
        #pragma unroll
        for (int jj = 0; jj < 3; jj++) {
            int j = threadIdx.x + jj * 256;
            const float4* p = (const float4*)&mtr[(i * N + j) * 8];
            float4 v0 = p[0], v1 = p[1];
            float4* q = (float4*)&g_mtrT[(j * N + i) * 8];
            q[0] = v0; q[1] = v1;
        }
        return;
    }
    // transposed weights: wT[i*OUT + o]  (broadcast reads, 16B-aligned float4 rows)
    __shared__ __align__(16) float wT0[20 * 32], wT1[32 * 32], wT2[32 * 32], wT3[32 * 64];
    __shared__ float sb0[32], sb1[32], sb2[32], sb3[64];
    int tid = threadIdx.x;
    for (int t = tid; t < 640; t += 256)  { int o = t / 20, i = t % 20; wT0[i * 32 + o] = w0[t]; }
    for (int t = tid; t < 1024; t += 256) { int o = t >> 5, i = t & 31; wT1[i * 32 + o] = w1[t]; wT2[i * 32 + o] = w2[t]; }
    for (int t = tid; t < 2048; t += 256) { int o = t >> 5, i = t & 31; wT3[i * 64 + o] = w3[t]; }
    if (tid < 32) { sb0[tid] = b0[tid]; sb1[tid] = b1[tid]; sb2[tid] = b2[tid]; }
    if (tid < 64) sb3[tid] = b3[tid];
    __syncthreads();

    int e = blockIdx.x * 256 + tid;
    int use64 = g_idx64;
    int s = load_idx(ei, e, use64);
    int d = load_idx(ei, E_N + e, use64);

    float x[20];
    {
        float4 v = *(const float4*)&ea[e * 4];
        x[0] = v.x; x[1] = v.y; x[2] = v.z; x[3] = v.w;
        v = *(const float4*)&feat[s * 8];     x[4] = v.x;  x[5] = v.y;  x[6] = v.z;  x[7] = v.w;
        v = *(const float4*)&feat[s * 8 + 4]; x[8] = v.x;  x[9] = v.y;  x[10] = v.z; x[11] = v.w;
        v = *(const float4*)&feat[d * 8];     x[12] = v.x; x[13] = v.y; x[14] = v.z; x[15] = v.w;
        v = *(const float4*)&feat[d * 8 + 4]; x[16] = v.x; x[17] = v.y; x[18] = v.z; x[19] = v.w;
    }

    float h[32], h2[32];
    // layer 0: 20 -> 32
    #pragma unroll
    for (int o = 0; o < 32; o++) h[o] = sb0[o];
    #pragma unroll
    for (int i = 0; i < 20; i++) {
        float xi = x[i];
        #pragma unroll
        for (int o = 0; o < 32; o += 4) {
            float4 w = *(const float4*)&wT0[i * 32 + o];
            h[o] += xi * w.x; h[o+1] += xi * w.y; h[o+2] += xi * w.z; h[o+3] += xi * w.w;
        }
    }
    #pragma unroll
    for (int o = 0; o < 32; o++) h[o] = fmaxf(h[o], 0.f);

    // layer 1: 32 -> 32
    #pragma unroll
    for (int o = 0; o < 32; o++) h2[o] = sb1[o];
    #pragma unroll
    for (int i = 0; i < 32; i++) {
        float xi = h[i];
        #pragma unroll
        for (int o = 0; o < 32; o += 4) {
            float4 w = *(const float4*)&wT1[i * 32 + o];
            h2[o] += xi * w.x; h2[o+1] += xi * w.y; h2[o+2] += xi * w.z; h2[o+3] += xi * w.w;
        }
    }
    #pragma unroll
    for (int o = 0; o < 32; o++) h2[o] = fmaxf(h2[o], 0.f);

    // layer 2: 32 -> 32
    #pragma unroll
    for (int o = 0; o < 32; o++) h[o] = sb2[o];
    #pragma unroll
    for (int i = 0; i < 32; i++) {
        float xi = h2[i];
        #pragma unroll
        for (int o = 0; o < 32; o += 4) {
            float4 w = *(const float4*)&wT2[i * 32 + o];
            h[o] += xi * w.x; h[o+1] += xi * w.y; h[o+2] += xi * w.z; h[o+3] += xi * w.w;
        }
    }
    #pragma unroll
    for (int o = 0; o < 32; o++) h[o] = fmaxf(h[o], 0.f);

    // layer 3: 32 -> 64 (no relu)
    float o64[64];
    #pragma unroll
    for (int o = 0; o < 64; o++) o64[o] = sb3[o];
    #pragma unroll
    for (int i = 0; i < 32; i++) {
        float xi = h[i];
        #pragma unroll
        for (int o = 0; o < 64; o += 4) {
            float4 w = *(const float4*)&wT3[i * 64 + o];
            o64[o] += xi * w.x; o64[o+1] += xi * w.y; o64[o+2] += xi * w.z; o64[o+3] += xi * w.w;
        }
    }
    #pragma unroll
    for (int c = 0; c < 64; c += 4) {
        float4 v; v.x = o64[c]; v.y = o64[c+1]; v.z = o64[c+2]; v.w = o64[c+3];
        *(float4*)&g_evals[e * 64 + c] = v;
    }
}

// -------- walk contraction: coalesced via g_mtrT, f32x2 packed over t --------
__global__ void k_walk(const void* __restrict__ ei) {
    int k = blockIdx.x;
    int tid = threadIdx.x;
    __shared__ __align__(16) float sM[8 * 64];
    __shared__ int ssrc[8];
    int cnt = g_cnt[k];
    int use64 = g_idx64;

    u64 acc[3][4];
    #pragma unroll
    for (int r = 0; r < 3; r++)
        #pragma unroll
        for (int t = 0; t < 4; t++) acc[r][t] = 0ULL;

    for (int base = 0; base < cnt; base += 8) {
        int nc = min(8, cnt - base);
        __syncthreads();
        for (int t = tid; t < nc * 64; t += 256) {
            int e = g_list[k * CAP + base + (t >> 6)];
            sM[t] = g_evals[e * 64 + (t & 63)];
        }
        if (tid < nc) ssrc[tid] = load_idx(ei, g_list[k * CAP + base + tid], use64);
        __syncthreads();

        for (int c = 0; c < nc; c++) {
            int s = ssrc[c];
            float av[3][8];
            #pragma unroll
            for (int r = 0; r < 3; r++) {
                int i = tid + (r << 8);
                const float4* p = (const float4*)&g_mtrT[(s * N + i) * 8];  // coalesced
                float4 v0 = p[0], v1 = p[1];
                av[r][0] = v0.x; av[r][1] = v0.y; av[r][2] = v0.z; av[r][3] = v0.w;
                av[r][4] = v1.x; av[r][5] = v1.y; av[r][6] = v1.z; av[r][7] = v1.w;
            }
            #pragma unroll
            for (int cc = 0; cc < 8; cc++) {
                const ulonglong2* mp = (const ulonglong2*)&sM[c * 64 + cc * 8];
                ulonglong2 ma = mp[0], mb = mp[1];
                #pragma unroll
                for (int r = 0; r < 3; r++) {
                    u64 dv = pk2(av[r][cc], av[r][cc]);
                    acc[r][0] = fma2(dv, ma.x, acc[r][0]);
                    acc[r][1] = fma2(dv, ma.y, acc[r][1]);
                    acc[r][2] = fma2(dv, mb.x, acc[r][2]);
                    acc[r][3] = fma2(dv, mb.y, acc[r][3]);
                }
            }
        }
    }
    u64 eighth = pk2(0.125f, 0.125f);
    #pragma unroll
    for (int r = 0; r < 3; r++) {
        int i = tid + (r << 8);
        float4 o0, o1;
        upk2(mul2(acc[r][0], eighth), o0.x, o0.y);
        upk2(mul2(acc[r][1], eighth), o0.z, o0.w);
        upk2(mul2(acc[r][2], eighth), o1.x, o1.y);
        upk2(mul2(acc[r][3], eighth), o1.z, o1.w);
        *(float4*)&g_mtr1[(i * N + k) * 8]     = o0;
        *(float4*)&g_mtr1[(i * N + k) * 8 + 4] = o1;
    }
}

// -------- output MLP: 2 rows/thread, f32x2, staged layer-0 to cap registers --------
__global__ void __launch_bounds__(128) k_out(
        const float* __restrict__ mtr, const float* __restrict__ feat,
        float* __restrict__ out,
        const float* __restrict__ w0, const float* __restrict__ b0,
        const float* __restrict__ w1, const float* __restrict__ b1,
        const float* __restrict__ w2, const float* __restrict__ b2,
        const float* __restrict__ w3, const float* __restrict__ b3) {
    // duplicated weight packs, transposed: wd[j*OUT + o] = (w[o][j], w[o][j])
    __shared__ __align__(16) u64 wd0[33 * 32], wd1[32 * 32], wd2[32 * 32], wd3[32 * 8];
    __shared__ __align__(16) u64 bd0[32], bd1[32], bd2[32], bd3[8];
    int tid = threadIdx.x;
    for (int t = tid; t < 1056; t += 128) { int j = t >> 5, o = t & 31; float w = w0[o * 33 + j]; wd0[t] = pk2(w, w); }
    for (int t = tid; t < 1024; t += 128) {
        int j = t >> 5, o = t & 31;
        float wa = w1[o * 32 + j]; wd1[t] = pk2(wa, wa);
        float wb = w2[o * 32 + j]; wd2[t] = pk2(wb, wb);
    }
    for (int t = tid; t < 256; t += 128) { int j = t >> 3, o = t & 7; float w = w3[o * 32 + j]; wd3[t] = pk2(w, w); }
    if (tid < 32) {
        float v;
        v = b0[tid]; bd0[tid] = pk2(v, v);
        v = b1[tid]; bd1[tid] = pk2(v, v);
        v = b2[tid]; bd2[tid] = pk2(v, v);
        if (tid < 8) { v = b3[tid]; bd3[tid] = pk2(v, v); }
    }
    __syncthreads();

    int i  = blockIdx.y;
    int k1 = blockIdx.x * 256 + tid;
    int k2 = k1 + 128;
    int base1 = (i * N + k1) * 8, base2 = (i * N + k2) * 8;
    int bT1 = (k1 * N + i) * 8, bT2 = (k2 * N + i) * 8;

    u64 acc[32], h[32];
    u64 xp[17];

    // ---- stage A: mtr1 inputs (j = 0..15) ----
    {
        float4 a0 = *(const float4*)&g_mtr1[base1], a1 = *(const float4*)&g_mtr1[base1 + 4];
        float4 c0 = *(const float4*)&g_mtr1[base2], c1 = *(const float4*)&g_mtr1[base2 + 4];
        xp[0] = pk2(a0.x, c0.x); xp[1] = pk2(a0.y, c0.y); xp[2] = pk2(a0.z, c0.z); xp[3] = pk2(a0.w, c0.w);
        xp[4] = pk2(a1.x, c1.x); xp[5] = pk2(a1.y, c1.y); xp[6] = pk2(a1.z, c1.z); xp[7] = pk2(a1.w, c1.w);
        a0 = *(const float4*)&g_mtr1[bT1]; a1 = *(const float4*)&g_mtr1[bT1 + 4];
        c0 = *(const float4*)&g_mtr1[bT2]; c1 = *(const float4*)&g_mtr1[bT2 + 4];
        xp[8]  = pk2(a0.x, c0.x); xp[9]  = pk2(a0.y, c0.y); xp[10] = pk2(a0.z, c0.z); xp[11] = pk2(a0.w, c0.w);
        xp[12] = pk2(a1.x, c1.x); xp[13] = pk2(a1.y, c1.y); xp[14] = pk2(a1.z, c1.z); xp[15] = pk2(a1.w, c1.w);
    }
    {
        const ulonglong2* B = (const ulonglong2*)bd0;
        #pragma unroll
        for (int oo = 0; oo < 16; oo++) { ulonglong2 b = B[oo]; acc[2*oo] = b.x; acc[2*oo+1] = b.y; }
        const ulonglong2* W = (const ulonglong2*)wd0;
        #pragma unroll
        for (int j = 0; j < 16; j++) {
            u64 xj = xp[j];
            #pragma unroll
            for (int oo = 0; oo < 16; oo++) {
                ulonglong2 w = W[j * 16 + oo];
                acc[2*oo]   = fma2(xj, w.x, acc[2*oo]);
                acc[2*oo+1] = fma2(xj, w.y, acc[2*oo+1]);
            }
        }
    }
    // ---- stage B: feat + eye inputs (j = 16..32) ----
    {
        float4 a0 = *(const float4*)&feat[k1 * 8], a1 = *(const float4*)&feat[k1 * 8 + 4];
        float4 c0 = *(const float4*)&feat[k2 * 8], c1 = *(const float4*)&feat[k2 * 8 + 4];
        xp[0] = pk2(a0.x, c0.x); xp[1] = pk2(a0.y, c0.y); xp[2] = pk2(a0.z, c0.z); xp[3] = pk2(a0.w, c0.w);
        xp[4] = pk2(a1.x, c1.x); xp[5] = pk2(a1.y, c1.y); xp[6] = pk2(a1.z, c1.z); xp[7] = pk2(a1.w, c1.w);
        a0 = *(const float4*)&feat[i * 8]; a1 = *(const float4*)&feat[i * 8 + 4];
        xp[8]  = pk2(a0.x, a0.x); xp[9]  = pk2(a0.y, a0.y); xp[10] = pk2(a0.z, a0.z); xp[11] = pk2(a0.w, a0.w);
        xp[12] = pk2(a1.x, a1.x); xp[13] = pk2(a1.y, a1.y); xp[14] = pk2(a1.z, a1.z); xp[15] = pk2(a1.w, a1.w);
        xp[16] = pk2(i == k1 ? 1.f : 0.f, i == k2 ? 1.f : 0.f);
    }
    {
        const ulonglong2* W = (const ulonglong2*)wd0;
        #pragma unroll
        for (int j = 0; j < 17; j++) {
            u64 xj = xp[j];
            #pragma unroll
            for (int oo = 0; oo < 16; oo++) {
                ulonglong2 w = W[(16 + j) * 16 + oo];
                acc[2*oo]   = fma2(xj, w.x, acc[2*oo]);
                acc[2*oo+1] = fma2(xj, w.y, acc[2*oo+1]);
            }
        }
        #pragma unroll
        for (int o = 0; o < 32; o++) h[o] = relu2(acc[o]);
    }
    // layer 1: 32 -> 32
    {
        const ulonglong2* B = (const ulonglong2*)bd1;
        #pragma unroll
        for (int oo = 0; oo < 16; oo++) { ulonglong2 b = B[oo]; acc[2*oo] = b.x; acc[2*oo+1] = b.y; }
        const ulonglong2* W = (const ulonglong2*)wd1;
        #pragma unroll
        for (int j = 0; j < 32; j++) {
            u64 xj = h[j];
            #pragma unroll
            for (int oo = 0; oo < 16; oo++) {
                ulonglong2 w = W[j * 16 + oo];
                acc[2*oo]   = fma2(xj, w.x, acc[2*oo]);
                acc[2*oo+1] = fma2(xj, w.y, acc[2*oo+1]);
            }
        }
        #pragma unroll
        for (int o = 0; o < 32; o++) acc[o] = relu2(acc[o]);
    }
    // layer 2: 32 -> 32
    {
        const ulonglong2* B = (const ulonglong2*)bd2;
        #pragma unroll
        for (int oo = 0; oo < 16; oo++) { ulonglong2 b = B[oo]; h[2*oo] = b.x; h[2*oo+1] = b.y; }
        const ulonglong2* W = (const ulonglong2*)wd2;
        #pragma unroll
        for (int j = 0; j < 32; j++) {
            u64 xj = acc[j];
            #pragma unroll
            for (int oo = 0; oo < 16; oo++) {
                ulonglong2 w = W[j * 16 + oo];
                h[2*oo]   = fma2(xj, w.x, h[2*oo]);
                h[2*oo+1] = fma2(xj, w.y, h[2*oo+1]);
            }
        }
        #pragma unroll
        for (int o = 0; o < 32; o++) h[o] = relu2(h[o]);
    }
    // layer 3: 32 -> 8
    u64 y[8];
    {
        const ulonglong2* B = (const ulonglong2*)bd3;
        #pragma unroll
        for (int oo = 0; oo < 4; oo++) { ulonglong2 b = B[oo]; y[2*oo] = b.x; y[2*oo+1] = b.y; }
        const ulonglong2* W = (const ulonglong2*)wd3;
        #pragma unroll
        for (int j = 0; j < 32; j++) {
            u64 xj = h[j];
            #pragma unroll
            for (int oo = 0; oo < 4; oo++) {
                ulonglong2 w = W[j * 4 + oo];
                y[2*oo]   = fma2(xj, w.x, y[2*oo]);
                y[2*oo+1] = fma2(xj, w.y, y[2*oo+1]);
            }
        }
    }
    // residual add + store both rows
    {
        float yr1[8], yr2[8];
        #pragma unroll
        for (int c = 0; c < 8; c++) upk2(y[c], yr1[c], yr2[c]);
        float4 m0 = *(const float4*)&mtr[base1], m1 = *(const float4*)&mtr[base1 + 4];
        float4 o0, o1;
        o0.x = m0.x + yr1[0]; o0.y = m0.y + yr1[1]; o0.z = m0.z + yr1[2]; o0.w = m0.w + yr1[3];
        o1.x = m1.x + yr1[4]; o1.y = m1.y + yr1[5]; o1.z = m1.z + yr1[6]; o1.w = m1.w + yr1[7];
        *(float4*)&out[base1] = o0; *(float4*)&out[base1 + 4] = o1;
        m0 = *(const float4*)&mtr[base2]; m1 = *(const float4*)&mtr[base2 + 4];
        o0.x = m0.x + yr2[0]; o0.y = m0.y + yr2[1]; o0.z = m0.z + yr2[2]; o0.w = m0.w + yr2[3];
        o1.x = m1.x + yr2[4]; o1.y = m1.y + yr2[5]; o1.z = m1.z + yr2[6]; o1.w = m1.w + yr2[7];
        *(float4*)&out[base2] = o0; *(float4*)&out[base2 + 4] = o1;
    }
}

extern "C" void kernel_launch(void* const* d_in, const int* in_sizes, int n_in,
                              void* d_out, int out_size) {
    const float* mtr  = (const float*)d_in[0];
    const float* feat = (const float*)d_in[1];
    const void*  ei   = d_in[2];
    const float* ea   = (const float*)d_in[3];
    const float* ew0 = (const float*)d_in[4],  *eb0 = (const float*)d_in[5];
    const float* ew1 = (const float*)d_in[6],  *eb1 = (const float*)d_in[7];
    const float* ew2 = (const float*)d_in[8],  *eb2 = (const float*)d_in[9];
    const float* ew3 = (const float*)d_in[10], *eb3 = (const float*)d_in[11];
    const float* ow0 = (const float*)d_in[12], *ob0 = (const float*)d_in[13];
    const float* ow1 = (const float*)d_in[14], *ob1 = (const float*)d_in[15];
    const float* ow2 = (const float*)d_in[16], *ob2 = (const float*)d_in[17];
    const float* ow3 = (const float*)d_in[18], *ob3 = (const float*)d_in[19];
    float* out = (float*)d_out;

    k_init<<<577, 1024>>>((const int*)ei);
    k_winner<<<E_N / 256, 256>>>(ei);
    k_build<<<E_N / 256, 256>>>(ei);
    k_edge<<<96 + 768, 256>>>(ei, ea, feat, mtr, ew0, eb0, ew1, eb1, ew2, eb2, ew3, eb3);
    k_walk<<<N, 256>>>(ei);
    dim3 g(3, N);
    k_out<<<g, 128>>>(mtr, feat, out, ow0, ob0, ow1, ob1, ow2, ob2, ow3, ob3);
}